// round 1
// baseline (speedup 1.0000x reference)
#include <cuda_runtime.h>
#include <cuda_bf16.h>
#include <math.h>

// Problem constants
#define B_  2
#define T_  2048
#define S_  2048
#define E_  1024
#define H_  16
#define D_  64
#define BT  (B_*T_)          // 4096
#define SCALE 0.125f          // 1/sqrt(64)

// Scratch (allocation-free rule: __device__ globals)
__device__ float g_Q[(size_t)BT * E_];    // [B,T,H,D] == [B,T,E]
__device__ float g_K[(size_t)BT * E_];    // [B,S,H,D]
__device__ float g_V[(size_t)BT * E_];
__device__ float g_C[(size_t)BT * E_];    // ctx [B,T,E]

// ---------------------------------------------------------------------------
// Dense NT SGEMM: C[M,N] = alpha * A[M,K] @ B[N,K]^T (+bias). lda=ldb=K, ldc=N.
// Tiles: 128x128x8, 256 threads, 8x8 per thread.
// ---------------------------------------------------------------------------
#define GBM 128
#define GBN 128
#define GBK 8

__global__ __launch_bounds__(256) void sgemm_nt(
    const float* __restrict__ A, const float* __restrict__ Bm,
    float* __restrict__ C, const float* __restrict__ bias,
    int M, int N, int K)
{
    __shared__ float As[GBK][GBM];
    __shared__ float Bs[GBK][GBN];

    const int tid = threadIdx.x;
    const int bm = blockIdx.y * GBM;
    const int bn = blockIdx.x * GBN;

    const int lr = tid >> 1;          // 0..127
    const int lc = (tid & 1) << 2;    // 0 or 4
    const int tm = (tid >> 4) << 3;   // row offset of 8x8 micro tile
    const int tn = (tid & 15) << 3;

    float acc[8][8];
    #pragma unroll
    for (int i = 0; i < 8; i++)
        #pragma unroll
        for (int j = 0; j < 8; j++) acc[i][j] = 0.f;

    for (int k0 = 0; k0 < K; k0 += GBK) {
        float4 av = *(const float4*)(A + (size_t)(bm + lr) * K + k0 + lc);
        As[lc + 0][lr] = av.x; As[lc + 1][lr] = av.y;
        As[lc + 2][lr] = av.z; As[lc + 3][lr] = av.w;
        float4 bv = *(const float4*)(Bm + (size_t)(bn + lr) * K + k0 + lc);
        Bs[lc + 0][lr] = bv.x; Bs[lc + 1][lr] = bv.y;
        Bs[lc + 2][lr] = bv.z; Bs[lc + 3][lr] = bv.w;
        __syncthreads();

        #pragma unroll
        for (int kk = 0; kk < GBK; kk++) {
            float a[8], b[8];
            #pragma unroll
            for (int i = 0; i < 8; i++) a[i] = As[kk][tm + i];
            #pragma unroll
            for (int j = 0; j < 8; j++) b[j] = Bs[kk][tn + j];
            #pragma unroll
            for (int i = 0; i < 8; i++)
                #pragma unroll
                for (int j = 0; j < 8; j++) acc[i][j] = fmaf(a[i], b[j], acc[i][j]);
        }
        __syncthreads();
    }

    #pragma unroll
    for (int i = 0; i < 8; i++) {
        float* crow = C + (size_t)(bm + tm + i) * N + bn + tn;
        #pragma unroll
        for (int j = 0; j < 8; j++) {
            float v = acc[i][j];
            if (bias) v += bias[bn + tn + j];
            crow[j] = v;
        }
    }
}

// ---------------------------------------------------------------------------
// Scores: per (b,h): S[t,s] = SCALE * Q_row(t) . K_row(s), D=64.
// Q/K laid out [B, T, H, D]; row stride 1024. Output attn[b,h,t,s] raw scores.
// Tiles 128x128x8, grid (16,16,32).
// ---------------------------------------------------------------------------
__global__ __launch_bounds__(256) void scores_kernel(
    const float* __restrict__ Q, const float* __restrict__ Kp,
    float* __restrict__ attn)
{
    const int z = blockIdx.z;
    const int b = z >> 4, h = z & 15;
    const float* Ab = Q  + (size_t)b * T_ * E_ + (size_t)h * D_;
    const float* Bb = Kp + (size_t)b * S_ * E_ + (size_t)h * D_;
    float* Cb = attn + (size_t)z * T_ * S_;

    __shared__ float As[GBK][GBM];
    __shared__ float Bs[GBK][GBN];

    const int tid = threadIdx.x;
    const int bm = blockIdx.y * GBM;
    const int bn = blockIdx.x * GBN;

    const int lr = tid >> 1;
    const int lc = (tid & 1) << 2;
    const int tm = (tid >> 4) << 3;
    const int tn = (tid & 15) << 3;

    float acc[8][8];
    #pragma unroll
    for (int i = 0; i < 8; i++)
        #pragma unroll
        for (int j = 0; j < 8; j++) acc[i][j] = 0.f;

    for (int k0 = 0; k0 < D_; k0 += GBK) {
        float4 av = *(const float4*)(Ab + (size_t)(bm + lr) * E_ + k0 + lc);
        As[lc + 0][lr] = av.x; As[lc + 1][lr] = av.y;
        As[lc + 2][lr] = av.z; As[lc + 3][lr] = av.w;
        float4 bv = *(const float4*)(Bb + (size_t)(bn + lr) * E_ + k0 + lc);
        Bs[lc + 0][lr] = bv.x; Bs[lc + 1][lr] = bv.y;
        Bs[lc + 2][lr] = bv.z; Bs[lc + 3][lr] = bv.w;
        __syncthreads();

        #pragma unroll
        for (int kk = 0; kk < GBK; kk++) {
            float a[8], b8[8];
            #pragma unroll
            for (int i = 0; i < 8; i++) a[i] = As[kk][tm + i];
            #pragma unroll
            for (int j = 0; j < 8; j++) b8[j] = Bs[kk][tn + j];
            #pragma unroll
            for (int i = 0; i < 8; i++)
                #pragma unroll
                for (int j = 0; j < 8; j++) acc[i][j] = fmaf(a[i], b8[j], acc[i][j]);
        }
        __syncthreads();
    }

    #pragma unroll
    for (int i = 0; i < 8; i++) {
        float* crow = Cb + (size_t)(bm + tm + i) * S_ + bn + tn;
        #pragma unroll
        for (int j = 0; j < 8; j++) crow[j] = acc[i][j] * SCALE;
    }
}

// ---------------------------------------------------------------------------
// Row softmax over S=2048. One block (256 threads) per row, data in registers.
// ---------------------------------------------------------------------------
__global__ __launch_bounds__(256) void softmax_kernel(float* __restrict__ attn)
{
    float* row = attn + (size_t)blockIdx.x * S_;
    const int tid = threadIdx.x;

    __shared__ float sh[8];

    float v[8];
    float m = -1e30f;
    #pragma unroll
    for (int i = 0; i < 8; i++) {
        v[i] = row[tid + (i << 8)];
        m = fmaxf(m, v[i]);
    }
    // block max
    #pragma unroll
    for (int o = 16; o > 0; o >>= 1) m = fmaxf(m, __shfl_xor_sync(0xffffffffu, m, o));
    if ((tid & 31) == 0) sh[tid >> 5] = m;
    __syncthreads();
    m = sh[0];
    #pragma unroll
    for (int i = 1; i < 8; i++) m = fmaxf(m, sh[i]);
    __syncthreads();

    float s = 0.f;
    #pragma unroll
    for (int i = 0; i < 8; i++) {
        v[i] = __expf(v[i] - m);
        s += v[i];
    }
    #pragma unroll
    for (int o = 16; o > 0; o >>= 1) s += __shfl_xor_sync(0xffffffffu, s, o);
    if ((tid & 31) == 0) sh[tid >> 5] = s;
    __syncthreads();
    s = sh[0];
    #pragma unroll
    for (int i = 1; i < 8; i++) s += sh[i];

    const float inv = 1.f / s;
    #pragma unroll
    for (int i = 0; i < 8; i++) row[tid + (i << 8)] = v[i] * inv;
}

// ---------------------------------------------------------------------------
// ctx: per (b,h): C[t,d] = sum_s attn[t,s] * V[b,s,h,d].  M=2048, N=64, K=2048.
// Tiles 64(M) x 64(N) x 16(K), 256 threads, 4x4 per thread. grid (32,1,32).
// ---------------------------------------------------------------------------
__global__ __launch_bounds__(256) void ctx_kernel(
    const float* __restrict__ attn, const float* __restrict__ V,
    float* __restrict__ C)
{
    const int z = blockIdx.z;
    const int b = z >> 4, h = z & 15;
    const float* Ab = attn + (size_t)z * T_ * S_;
    const float* Bb = V + (size_t)b * S_ * E_ + (size_t)h * D_;
    float* Cb = C + (size_t)b * T_ * E_ + (size_t)h * D_;

    __shared__ float As[64][17];
    __shared__ float Bs[16][64];

    const int tid = threadIdx.x;
    const int bm = blockIdx.x * 64;
    const int tm = (tid >> 4) << 2;
    const int tn = (tid & 15) << 2;

    float acc[4][4];
    #pragma unroll
    for (int i = 0; i < 4; i++)
        #pragma unroll
        for (int j = 0; j < 4; j++) acc[i][j] = 0.f;

    for (int k0 = 0; k0 < S_; k0 += 16) {
        const int lr = tid >> 2;          // 0..63
        const int lc = (tid & 3) << 2;    // 0,4,8,12
        float4 av = *(const float4*)(Ab + (size_t)(bm + lr) * S_ + k0 + lc);
        As[lr][lc + 0] = av.x; As[lr][lc + 1] = av.y;
        As[lr][lc + 2] = av.z; As[lr][lc + 3] = av.w;

        const int kr = tid >> 4;          // 0..15
        const int nc = (tid & 15) << 2;   // 0..60
        float4 bv = *(const float4*)(Bb + (size_t)(k0 + kr) * E_ + nc);
        Bs[kr][nc + 0] = bv.x; Bs[kr][nc + 1] = bv.y;
        Bs[kr][nc + 2] = bv.z; Bs[kr][nc + 3] = bv.w;
        __syncthreads();

        #pragma unroll
        for (int kk = 0; kk < 16; kk++) {
            float a[4], b4[4];
            #pragma unroll
            for (int i = 0; i < 4; i++) a[i] = As[tm + i][kk];
            #pragma unroll
            for (int j = 0; j < 4; j++) b4[j] = Bs[kk][tn + j];
            #pragma unroll
            for (int i = 0; i < 4; i++)
                #pragma unroll
                for (int j = 0; j < 4; j++) acc[i][j] = fmaf(a[i], b4[j], acc[i][j]);
        }
        __syncthreads();
    }

    #pragma unroll
    for (int i = 0; i < 4; i++) {
        float* crow = Cb + (size_t)(bm + tm + i) * E_ + tn;
        #pragma unroll
        for (int j = 0; j < 4; j++) crow[j] = acc[i][j];
    }
}

// ---------------------------------------------------------------------------
extern "C" void kernel_launch(void* const* d_in, const int* in_sizes, int n_in,
                              void* d_out, int out_size)
{
    const float* src = (const float*)d_in[0];   // source_emb [2,2048,1024]
    const float* tgt = (const float*)d_in[1];   // target_emb [2,2048,1024]
    const float* Wq  = (const float*)d_in[2];
    const float* Wk  = (const float*)d_in[3];
    const float* Wv  = (const float*)d_in[4];
    const float* Wo  = (const float*)d_in[5];
    const float* bo  = (const float*)d_in[6];

    float* out  = (float*)d_out;
    float* attn = out + (size_t)BT * E_;        // out first, then attn

    float *Qp, *Kp, *Vp, *Cp;
    cudaGetSymbolAddress((void**)&Qp, g_Q);
    cudaGetSymbolAddress((void**)&Kp, g_K);
    cudaGetSymbolAddress((void**)&Vp, g_V);
    cudaGetSymbolAddress((void**)&Cp, g_C);

    dim3 blk(256);
    dim3 gproj(E_ / GBN, BT / GBM);             // (8, 32)

    sgemm_nt<<<gproj, blk>>>(tgt, Wq, Qp, nullptr, BT, E_, E_);
    sgemm_nt<<<gproj, blk>>>(src, Wk, Kp, nullptr, BT, E_, E_);
    sgemm_nt<<<gproj, blk>>>(src, Wv, Vp, nullptr, BT, E_, E_);

    scores_kernel<<<dim3(S_ / GBN, T_ / GBM, B_ * H_), blk>>>(Qp, Kp, attn);

    softmax_kernel<<<B_ * H_ * T_, 256>>>(attn);

    ctx_kernel<<<dim3(T_ / 64, 1, B_ * H_), blk>>>(attn, Vp, Cp);

    sgemm_nt<<<gproj, blk>>>(Cp, Wo, out, bo, BT, E_, E_);
}

// round 3
// speedup vs baseline: 1.9957x; 1.9957x over previous
#include <cuda_runtime.h>
#include <cuda_bf16.h>
#include <stdint.h>
#include <math.h>

#define B_  2
#define T_  2048
#define S_  2048
#define E_  1024
#define H_  16
#define D_  64
#define BT  (B_*T_)
#define SCALE 0.125f

// Scratch (allocation-free rule)
__device__ float g_Q[(size_t)BT * E_];
__device__ float g_K[(size_t)BT * E_];
__device__ float g_V[(size_t)BT * E_];
__device__ float g_C[(size_t)BT * E_];

// fp32 -> (bf16 hi, bf16 lo) for a pair of consecutive-k values packed as bf16x2
__device__ __forceinline__ void cvt_hilo2(float x0, float x1, uint32_t& h, uint32_t& l) {
    asm("cvt.rn.bf16x2.f32 %0, %1, %2;" : "=r"(h) : "f"(x1), "f"(x0));
    float h0 = __uint_as_float(h << 16);
    float h1 = __uint_as_float(h & 0xffff0000u);
    asm("cvt.rn.bf16x2.f32 %0, %1, %2;" : "=r"(l) : "f"(x1 - h1), "f"(x0 - h0));
}

__device__ __forceinline__ void mma16816(float c[4], const uint32_t a[4], const uint32_t b[2]) {
    asm volatile("mma.sync.aligned.m16n8k16.row.col.f32.bf16.bf16.f32 "
        "{%0,%1,%2,%3}, {%4,%5,%6,%7}, {%8,%9}, {%0,%1,%2,%3};"
        : "+f"(c[0]), "+f"(c[1]), "+f"(c[2]), "+f"(c[3])
        : "r"(a[0]), "r"(a[1]), "r"(a[2]), "r"(a[3]), "r"(b[0]), "r"(b[1]));
}

// ---------------------------------------------------------------------------
// Generic block GEMM core, bf16x3 emulated fp32.
// C[M,N] = alpha * A[M,K] @ op(B) (+bias), A row-major [m,k] (lda),
// BNT=true : B is [N,K] row-major (NT gemm), BNT=false: B is [K,N] (NN, BN=64).
// Block tile: 128 x BN x 16, 256 threads (8 warps).
// ---------------------------------------------------------------------------
template<int BN, bool BNT>
__device__ __forceinline__ void gemm_core(
    const float* __restrict__ A, const float* __restrict__ Bm,
    float* __restrict__ C, const float* __restrict__ bias,
    int K, int lda, int ldb, int ldc, float alpha)
{
    constexpr int BM = 128, BK = 16, LDSH = 24;     // 24 bf16 row stride (48B)
    constexpr int NWN = (BN == 128) ? 4 : 2;
    constexpr int NWM = 8 / NWN;
    constexpr int WM = BM / NWM;                     // 64 or 32
    constexpr int MT = WM / 16;                      // 4 or 2
    constexpr int NT = 4;                            // warp covers 32 cols

    __shared__ __align__(16) __nv_bfloat16 Ah[BM][LDSH];
    __shared__ __align__(16) __nv_bfloat16 Al[BM][LDSH];
    __shared__ __align__(16) __nv_bfloat16 Bh[BN][LDSH];
    __shared__ __align__(16) __nv_bfloat16 Bl[BN][LDSH];

    const int tid  = threadIdx.x;
    const int lane = tid & 31, wid = tid >> 5;
    const int wm = wid / NWN, wn = wid % NWN;
    const int bm = blockIdx.y * BM, bn = blockIdx.x * BN;
    const int rr = lane >> 2;            // 0..7
    const int kq = (lane & 3) << 1;      // 0,2,4,6

    float acc[MT][NT][4] = {};

    for (int k0 = 0; k0 < K; k0 += BK) {
        // ---- A tile: 128x16 fp32 -> hi/lo bf16 smem ----
        {
            const int col = (tid & 3) << 2;
            const int row = tid >> 2;    // 0..63
            #pragma unroll
            for (int half = 0; half < 2; half++) {
                int r = row + half * 64;
                float4 v = *(const float4*)(A + (size_t)(bm + r) * lda + k0 + col);
                uint32_t h01, l01, h23, l23;
                cvt_hilo2(v.x, v.y, h01, l01);
                cvt_hilo2(v.z, v.w, h23, l23);
                *(uint2*)&Ah[r][col] = make_uint2(h01, h23);
                *(uint2*)&Al[r][col] = make_uint2(l01, l23);
            }
        }
        // ---- B tile ----
        if (BNT) {
            const int col = (tid & 3) << 2;
            const int row = tid >> 2;
            #pragma unroll
            for (int half = 0; half < BN / 64; half++) {
                int r = row + half * 64;
                float4 v = *(const float4*)(Bm + (size_t)(bn + r) * ldb + k0 + col);
                uint32_t h01, l01, h23, l23;
                cvt_hilo2(v.x, v.y, h01, l01);
                cvt_hilo2(v.z, v.w, h23, l23);
                *(uint2*)&Bh[r][col] = make_uint2(h01, h23);
                *(uint2*)&Bl[r][col] = make_uint2(l01, l23);
            }
        } else {
            // BN == 64: load 16(k) x 64(n) from B[k][n], transpose into [n][k]
            const int n4 = (tid & 15) << 2;
            const int k  = tid >> 4;     // 0..15
            float4 v = *(const float4*)(Bm + (size_t)(k0 + k) * ldb + bn + n4);
            float vv[4] = {v.x, v.y, v.z, v.w};
            #pragma unroll
            for (int j = 0; j < 4; j++) {
                __nv_bfloat16 hb = __float2bfloat16(vv[j]);
                float hf = __bfloat162float(hb);
                __nv_bfloat16 lb = __float2bfloat16(vv[j] - hf);
                Bh[n4 + j][k] = hb;
                Bl[n4 + j][k] = lb;
            }
        }
        __syncthreads();

        // ---- fragments + MMA ----
        uint32_t bh[NT][2], bl[NT][2];
        #pragma unroll
        for (int nt = 0; nt < NT; nt++) {
            int n = wn * 32 + nt * 8 + rr;
            bh[nt][0] = *(const uint32_t*)&Bh[n][kq];
            bh[nt][1] = *(const uint32_t*)&Bh[n][kq + 8];
            bl[nt][0] = *(const uint32_t*)&Bl[n][kq];
            bl[nt][1] = *(const uint32_t*)&Bl[n][kq + 8];
        }
        #pragma unroll
        for (int mt = 0; mt < MT; mt++) {
            uint32_t ah[4], al[4];
            int m = wm * WM + mt * 16 + rr;
            ah[0] = *(const uint32_t*)&Ah[m][kq];
            ah[1] = *(const uint32_t*)&Ah[m + 8][kq];
            ah[2] = *(const uint32_t*)&Ah[m][kq + 8];
            ah[3] = *(const uint32_t*)&Ah[m + 8][kq + 8];
            al[0] = *(const uint32_t*)&Al[m][kq];
            al[1] = *(const uint32_t*)&Al[m + 8][kq];
            al[2] = *(const uint32_t*)&Al[m][kq + 8];
            al[3] = *(const uint32_t*)&Al[m + 8][kq + 8];
            #pragma unroll
            for (int nt = 0; nt < NT; nt++) {
                mma16816(acc[mt][nt], ah, bh[nt]);   // hi*hi
                mma16816(acc[mt][nt], al, bh[nt]);   // lo*hi
                mma16816(acc[mt][nt], ah, bl[nt]);   // hi*lo
            }
        }
        __syncthreads();
    }

    // ---- epilogue ----
    #pragma unroll
    for (int mt = 0; mt < MT; mt++) {
        int m0 = bm + wm * WM + mt * 16 + rr;
        #pragma unroll
        for (int nt = 0; nt < NT; nt++) {
            int n = bn + wn * 32 + nt * 8 + kq;
            float b0 = bias ? bias[n] : 0.f;
            float b1 = bias ? bias[n + 1] : 0.f;
            float* p0 = C + (size_t)m0 * ldc + n;
            p0[0] = acc[mt][nt][0] * alpha + b0;
            p0[1] = acc[mt][nt][1] * alpha + b1;
            float* p1 = C + (size_t)(m0 + 8) * ldc + n;
            p1[0] = acc[mt][nt][2] * alpha + b0;
            p1[1] = acc[mt][nt][3] * alpha + b1;
        }
    }
}

// ---- wrappers ----
__global__ __launch_bounds__(256) void k_dense(
    const float* __restrict__ A, const float* __restrict__ Bm,
    float* __restrict__ C, const float* __restrict__ bias)
{
    gemm_core<128, true>(A, Bm, C, bias, E_, E_, E_, E_, 1.0f);
}

__global__ __launch_bounds__(256) void k_scores(
    const float* __restrict__ Q, const float* __restrict__ Kp,
    float* __restrict__ attn)
{
    const int z = blockIdx.z;
    const int b = z >> 4, h = z & 15;
    const float* Ab = Q  + (size_t)b * T_ * E_ + (size_t)h * D_;
    const float* Bb = Kp + (size_t)b * S_ * E_ + (size_t)h * D_;
    float* Cb = attn + (size_t)z * T_ * S_;
    gemm_core<128, true>(Ab, Bb, Cb, nullptr, D_, E_, E_, S_, SCALE);
}

__global__ __launch_bounds__(256) void k_ctx(
    const float* __restrict__ attn, const float* __restrict__ V,
    float* __restrict__ C)
{
    const int z = blockIdx.z;
    const int b = z >> 4, h = z & 15;
    const float* Ab = attn + (size_t)z * T_ * S_;
    const float* Bb = V + (size_t)b * S_ * E_ + (size_t)h * D_;
    float* Cb = C + (size_t)b * T_ * E_ + (size_t)h * D_;
    gemm_core<64, false>(Ab, Bb, Cb, nullptr, S_, S_, E_, E_, 1.0f);
}

// ---------------------------------------------------------------------------
// Row softmax over S=2048. One block (256 threads) per row.
// ---------------------------------------------------------------------------
__global__ __launch_bounds__(256) void softmax_kernel(float* __restrict__ attn)
{
    float* row = attn + (size_t)blockIdx.x * S_;
    const int tid = threadIdx.x;
    __shared__ float sh[8];

    float v[8];
    float m = -1e30f;
    #pragma unroll
    for (int i = 0; i < 8; i++) {
        v[i] = row[tid + (i << 8)];
        m = fmaxf(m, v[i]);
    }
    #pragma unroll
    for (int o = 16; o > 0; o >>= 1) m = fmaxf(m, __shfl_xor_sync(0xffffffffu, m, o));
    if ((tid & 31) == 0) sh[tid >> 5] = m;
    __syncthreads();
    m = sh[0];
    #pragma unroll
    for (int i = 1; i < 8; i++) m = fmaxf(m, sh[i]);
    __syncthreads();

    float s = 0.f;
    #pragma unroll
    for (int i = 0; i < 8; i++) {
        v[i] = __expf(v[i] - m);
        s += v[i];
    }
    #pragma unroll
    for (int o = 16; o > 0; o >>= 1) s += __shfl_xor_sync(0xffffffffu, s, o);
    if ((tid & 31) == 0) sh[tid >> 5] = s;
    __syncthreads();
    s = sh[0];
    #pragma unroll
    for (int i = 1; i < 8; i++) s += sh[i];

    const float inv = 1.f / s;
    #pragma unroll
    for (int i = 0; i < 8; i++) row[tid + (i << 8)] = v[i] * inv;
}

// ---------------------------------------------------------------------------
extern "C" void kernel_launch(void* const* d_in, const int* in_sizes, int n_in,
                              void* d_out, int out_size)
{
    const float* src = (const float*)d_in[0];
    const float* tgt = (const float*)d_in[1];
    const float* Wq  = (const float*)d_in[2];
    const float* Wk  = (const float*)d_in[3];
    const float* Wv  = (const float*)d_in[4];
    const float* Wo  = (const float*)d_in[5];
    const float* bo  = (const float*)d_in[6];

    float* out  = (float*)d_out;
    float* attn = out + (size_t)BT * E_;

    float *Qp, *Kp, *Vp, *Cp;
    cudaGetSymbolAddress((void**)&Qp, g_Q);
    cudaGetSymbolAddress((void**)&Kp, g_K);
    cudaGetSymbolAddress((void**)&Vp, g_V);
    cudaGetSymbolAddress((void**)&Cp, g_C);

    dim3 blk(256);
    dim3 gproj(E_ / 128, BT / 128);              // (8, 32)

    k_dense<<<gproj, blk>>>(tgt, Wq, Qp, nullptr);
    k_dense<<<gproj, blk>>>(src, Wk, Kp, nullptr);
    k_dense<<<gproj, blk>>>(src, Wv, Vp, nullptr);

    k_scores<<<dim3(S_ / 128, T_ / 128, B_ * H_), blk>>>(Qp, Kp, attn);

    softmax_kernel<<<B_ * H_ * T_, 256>>>(attn);

    k_ctx<<<dim3(1, T_ / 128, B_ * H_), blk>>>(attn, Vp, Cp);

    k_dense<<<gproj, blk>>>(Cp, Wo, out, bo);
}

// round 4
// speedup vs baseline: 2.0788x; 1.0416x over previous
#include <cuda_runtime.h>
#include <cuda_bf16.h>
#include <stdint.h>

#define B_  2
#define T_  2048
#define S_  2048
#define E_  1024
#define H_  16
#define D_  64
#define BT  (B_*T_)
#define Z_  (B_*H_)
#define SCALE 0.125f

// Scratch (allocation-free rule: __device__ globals)
__device__ __nv_bfloat16 g_Qh[(size_t)Z_*T_*D_], g_Ql[(size_t)Z_*T_*D_];
__device__ __nv_bfloat16 g_Kh[(size_t)Z_*S_*D_], g_Kl[(size_t)Z_*S_*D_];
__device__ __nv_bfloat16 g_Vh[(size_t)Z_*S_*D_], g_Vl[(size_t)Z_*S_*D_];
__device__ float g_C[(size_t)BT*E_];
__device__ float g_rs[(size_t)Z_*T_];

// fp32 pair -> bf16x2 hi + bf16x2 lo
__device__ __forceinline__ void cvt_hilo2(float x0, float x1, uint32_t& h, uint32_t& l) {
    asm("cvt.rn.bf16x2.f32 %0, %1, %2;" : "=r"(h) : "f"(x1), "f"(x0));
    float h0 = __uint_as_float(h << 16);
    float h1 = __uint_as_float(h & 0xffff0000u);
    asm("cvt.rn.bf16x2.f32 %0, %1, %2;" : "=r"(l) : "f"(x1 - h1), "f"(x0 - h0));
}

__device__ __forceinline__ void mma16816(float c[4], const uint32_t a[4], const uint32_t b[2]) {
    asm volatile("mma.sync.aligned.m16n8k16.row.col.f32.bf16.bf16.f32 "
        "{%0,%1,%2,%3}, {%4,%5,%6,%7}, {%8,%9}, {%0,%1,%2,%3};"
        : "+f"(c[0]), "+f"(c[1]), "+f"(c[2]), "+f"(c[3])
        : "r"(a[0]), "r"(a[1]), "r"(a[2]), "r"(a[3]), "r"(b[0]), "r"(b[1]));
}

// Fast exp on the FMA pipe: 2^(x*log2e), deg-6 poly, magic-number rounding.
// Rel err ~2e-7 for |x| < 60. No MUFU.
__device__ __forceinline__ float fast_exp(float x) {
    const float MAGIC = 12582912.0f;                    // 1.5 * 2^23
    float t = x * 1.44269504088896f;
    float r = t + MAGIC;
    int ib = __float_as_int(r);
    float f = t - (r - MAGIC);                          // f in [-0.5, 0.5]
    float p = 1.54035304e-4f;
    p = fmaf(p, f, 1.33335581e-3f);
    p = fmaf(p, f, 9.61812911e-3f);
    p = fmaf(p, f, 5.55041087e-2f);
    p = fmaf(p, f, 2.40226507e-1f);
    p = fmaf(p, f, 6.93147182e-1f);
    p = fmaf(p, f, 1.0f);
    float s = __int_as_float((ib + 127) << 23);
    return p * s;
}

// ---------------------------------------------------------------------------
// Dense NT GEMM 128x128x16, bf16x3. TO_HL=true: write bf16 hi/lo head-major.
// TO_HL=false: write fp32 C (+bias).
// ---------------------------------------------------------------------------
template<bool TO_HL>
__global__ __launch_bounds__(256) void k_proj(
    const float* __restrict__ A, const float* __restrict__ Bm,
    float* __restrict__ C, const float* __restrict__ bias,
    __nv_bfloat16* __restrict__ Oh, __nv_bfloat16* __restrict__ Ol)
{
    constexpr int BM = 128, BN = 128, BK = 16, LDSH = 24;
    constexpr int K = E_;

    __shared__ __align__(16) __nv_bfloat16 Ah[BM][LDSH];
    __shared__ __align__(16) __nv_bfloat16 Al[BM][LDSH];
    __shared__ __align__(16) __nv_bfloat16 Bh[BN][LDSH];
    __shared__ __align__(16) __nv_bfloat16 Bl[BN][LDSH];

    const int tid  = threadIdx.x;
    const int lane = tid & 31, wid = tid >> 5;
    const int wm = wid >> 2, wn = wid & 3;           // 2 x 4 warps
    const int bm = blockIdx.y * BM, bn = blockIdx.x * BN;
    const int rr = lane >> 2;
    const int q2 = (lane & 3) << 1;

    float acc[4][4][4] = {};                          // MT=4, NT=4

    for (int k0 = 0; k0 < K; k0 += BK) {
        const int col = (tid & 3) << 2;
        const int row = tid >> 2;
        #pragma unroll
        for (int half = 0; half < 2; half++) {
            int r = row + half * 64;
            float4 v = *(const float4*)(A + (size_t)(bm + r) * K + k0 + col);
            uint32_t h01, l01, h23, l23;
            cvt_hilo2(v.x, v.y, h01, l01);
            cvt_hilo2(v.z, v.w, h23, l23);
            *(uint2*)&Ah[r][col] = make_uint2(h01, h23);
            *(uint2*)&Al[r][col] = make_uint2(l01, l23);
            float4 w = *(const float4*)(Bm + (size_t)(bn + r) * K + k0 + col);
            cvt_hilo2(w.x, w.y, h01, l01);
            cvt_hilo2(w.z, w.w, h23, l23);
            *(uint2*)&Bh[r][col] = make_uint2(h01, h23);
            *(uint2*)&Bl[r][col] = make_uint2(l01, l23);
        }
        __syncthreads();

        uint32_t bh[4][2], bl[4][2];
        #pragma unroll
        for (int nt = 0; nt < 4; nt++) {
            int n = wn * 32 + nt * 8 + rr;
            bh[nt][0] = *(const uint32_t*)&Bh[n][q2];
            bh[nt][1] = *(const uint32_t*)&Bh[n][q2 + 8];
            bl[nt][0] = *(const uint32_t*)&Bl[n][q2];
            bl[nt][1] = *(const uint32_t*)&Bl[n][q2 + 8];
        }
        #pragma unroll
        for (int mt = 0; mt < 4; mt++) {
            uint32_t ah[4], al[4];
            int m = wm * 64 + mt * 16 + rr;
            ah[0] = *(const uint32_t*)&Ah[m][q2];
            ah[1] = *(const uint32_t*)&Ah[m + 8][q2];
            ah[2] = *(const uint32_t*)&Ah[m][q2 + 8];
            ah[3] = *(const uint32_t*)&Ah[m + 8][q2 + 8];
            al[0] = *(const uint32_t*)&Al[m][q2];
            al[1] = *(const uint32_t*)&Al[m + 8][q2];
            al[2] = *(const uint32_t*)&Al[m][q2 + 8];
            al[3] = *(const uint32_t*)&Al[m + 8][q2 + 8];
            #pragma unroll
            for (int nt = 0; nt < 4; nt++) {
                mma16816(acc[mt][nt], ah, bh[nt]);
                mma16816(acc[mt][nt], al, bh[nt]);
                mma16816(acc[mt][nt], ah, bl[nt]);
            }
        }
        __syncthreads();
    }

    #pragma unroll
    for (int mt = 0; mt < 4; mt++) {
        #pragma unroll
        for (int nt = 0; nt < 4; nt++) {
            int n = bn + wn * 32 + nt * 8 + q2;
            #pragma unroll
            for (int rh = 0; rh < 2; rh++) {
                int m = bm + wm * 64 + mt * 16 + rr + rh * 8;
                float v0 = acc[mt][nt][rh * 2 + 0];
                float v1 = acc[mt][nt][rh * 2 + 1];
                if (TO_HL) {
                    int b = m >> 11, t = m & 2047;
                    int h = n >> 6, d = n & 63;
                    size_t off = ((size_t)(b * H_ + h) * T_ + t) * D_ + d;
                    uint32_t hh, ll;
                    cvt_hilo2(v0, v1, hh, ll);
                    *(uint32_t*)&Oh[off] = hh;
                    *(uint32_t*)&Ol[off] = ll;
                } else {
                    float* p = C + (size_t)m * E_ + n;
                    p[0] = v0 + (bias ? bias[n] : 0.f);
                    p[1] = v1 + (bias ? bias[n + 1] : 0.f);
                }
            }
        }
    }
}

// ---------------------------------------------------------------------------
// Fused scores + exp: per (z, t-block 128): stream 16 K-tiles of 128,
// MMA bf16x3, e=fast_exp(score*SCALE), write e (unnormalized) to attn,
// accumulate row sums -> g_rs.
// ---------------------------------------------------------------------------
#define LDQ 72   // bf16 smem row stride for 64-wide tiles (conflict-free)

__global__ __launch_bounds__(256) void k_sco(float* __restrict__ attn)
{
    extern __shared__ __nv_bfloat16 sm[];
    __nv_bfloat16* Qh = sm;
    __nv_bfloat16* Ql = sm + 128 * LDQ;
    __nv_bfloat16* Kh = sm + 2 * 128 * LDQ;
    __nv_bfloat16* Kl = sm + 3 * 128 * LDQ;
    __shared__ float rs[128];

    const int tid = threadIdx.x, lane = tid & 31, wid = tid >> 5;
    const int wm = wid >> 1, wn = wid & 1;      // 4 x 2 warps, warp tile 32x64
    const int rr = lane >> 2, q2 = (lane & 3) << 1;
    const int z = blockIdx.y;
    const int t0 = blockIdx.x * 128;

    const __nv_bfloat16* Qhg = g_Qh + ((size_t)z * T_ + t0) * D_;
    const __nv_bfloat16* Qlg = g_Ql + ((size_t)z * T_ + t0) * D_;
    const __nv_bfloat16* Khg = g_Kh + (size_t)z * S_ * D_;
    const __nv_bfloat16* Klg = g_Kl + (size_t)z * S_ * D_;
    float* Ab = attn + (size_t)z * T_ * S_;

    if (tid < 128) rs[tid] = 0.f;

    #pragma unroll
    for (int i = 0; i < 4; i++) {
        int idx = tid + i * 256;
        int r = idx >> 3, c = (idx & 7) << 3;
        *(uint4*)&Qh[r * LDQ + c] = *(const uint4*)&Qhg[r * D_ + c];
        *(uint4*)&Ql[r * LDQ + c] = *(const uint4*)&Qlg[r * D_ + c];
    }

    float psum[2][2] = {};

    for (int si = 0; si < 16; si++) {
        __syncthreads();
        const __nv_bfloat16* Kt = Khg + (size_t)si * 128 * D_;
        const __nv_bfloat16* Lt = Klg + (size_t)si * 128 * D_;
        #pragma unroll
        for (int i = 0; i < 4; i++) {
            int idx = tid + i * 256;
            int r = idx >> 3, c = (idx & 7) << 3;
            *(uint4*)&Kh[r * LDQ + c] = *(const uint4*)&Kt[r * D_ + c];
            *(uint4*)&Kl[r * LDQ + c] = *(const uint4*)&Lt[r * D_ + c];
        }
        __syncthreads();

        float acc[2][8][4] = {};
        #pragma unroll
        for (int ks = 0; ks < 4; ks++) {
            const int kq = ks * 16 + q2;
            uint32_t ah[2][4], al[2][4];
            #pragma unroll
            for (int mt = 0; mt < 2; mt++) {
                int m = wm * 32 + mt * 16 + rr;
                ah[mt][0] = *(const uint32_t*)&Qh[m * LDQ + kq];
                ah[mt][1] = *(const uint32_t*)&Qh[(m + 8) * LDQ + kq];
                ah[mt][2] = *(const uint32_t*)&Qh[m * LDQ + kq + 8];
                ah[mt][3] = *(const uint32_t*)&Qh[(m + 8) * LDQ + kq + 8];
                al[mt][0] = *(const uint32_t*)&Ql[m * LDQ + kq];
                al[mt][1] = *(const uint32_t*)&Ql[(m + 8) * LDQ + kq];
                al[mt][2] = *(const uint32_t*)&Ql[m * LDQ + kq + 8];
                al[mt][3] = *(const uint32_t*)&Ql[(m + 8) * LDQ + kq + 8];
            }
            #pragma unroll
            for (int nt = 0; nt < 8; nt++) {
                int n = wn * 64 + nt * 8 + rr;
                uint32_t bh[2] = { *(const uint32_t*)&Kh[n * LDQ + kq],
                                   *(const uint32_t*)&Kh[n * LDQ + kq + 8] };
                uint32_t bl[2] = { *(const uint32_t*)&Kl[n * LDQ + kq],
                                   *(const uint32_t*)&Kl[n * LDQ + kq + 8] };
                #pragma unroll
                for (int mt = 0; mt < 2; mt++) {
                    mma16816(acc[mt][nt], ah[mt], bh);
                    mma16816(acc[mt][nt], al[mt], bh);
                    mma16816(acc[mt][nt], ah[mt], bl);
                }
            }
        }

        #pragma unroll
        for (int mt = 0; mt < 2; mt++) {
            int r0 = t0 + wm * 32 + mt * 16 + rr;
            #pragma unroll
            for (int nt = 0; nt < 8; nt++) {
                int n0 = si * 128 + wn * 64 + nt * 8 + q2;
                float e0 = fast_exp(acc[mt][nt][0] * SCALE);
                float e1 = fast_exp(acc[mt][nt][1] * SCALE);
                float e2 = fast_exp(acc[mt][nt][2] * SCALE);
                float e3 = fast_exp(acc[mt][nt][3] * SCALE);
                psum[mt][0] += e0 + e1;
                psum[mt][1] += e2 + e3;
                *(float2*)&Ab[(size_t)r0 * S_ + n0]       = make_float2(e0, e1);
                *(float2*)&Ab[(size_t)(r0 + 8) * S_ + n0] = make_float2(e2, e3);
            }
        }
    }

    __syncthreads();
    #pragma unroll
    for (int mt = 0; mt < 2; mt++) {
        atomicAdd(&rs[wm * 32 + mt * 16 + rr], psum[mt][0]);
        atomicAdd(&rs[wm * 32 + mt * 16 + rr + 8], psum[mt][1]);
    }
    __syncthreads();
    if (tid < 128) g_rs[(size_t)z * T_ + t0 + tid] = rs[tid];
}

// ---------------------------------------------------------------------------
// Fused normalize + ctx: per (z, t-block 128): stream attn e-tiles (128x32),
// p = e * inv_rowsum -> write final attn in-place; bf16x3 MMA P @ V -> g_C.
// ---------------------------------------------------------------------------
__global__ __launch_bounds__(256) void k_ctx(float* __restrict__ attn)
{
    __shared__ __align__(16) __nv_bfloat16 Ph[128][40], Pl[128][40];
    __shared__ __align__(16) __nv_bfloat16 Vh[64][40], Vl[64][40];
    __shared__ float inv_s[128];

    const int tid = threadIdx.x, lane = tid & 31, wid = tid >> 5;
    const int wm = wid >> 1, wn = wid & 1;      // 4 x 2, warp tile 32x32
    const int rr = lane >> 2, q2 = (lane & 3) << 1;
    const int z = blockIdx.y, t0 = blockIdx.x * 128;
    const int b = z >> 4, h = z & 15;

    float* Ab = attn + ((size_t)z * T_ + t0) * S_;
    const __nv_bfloat16* Vhg = g_Vh + (size_t)z * S_ * D_;
    const __nv_bfloat16* Vlg = g_Vl + (size_t)z * S_ * D_;

    if (tid < 128) inv_s[tid] = 1.0f / g_rs[(size_t)z * T_ + t0 + tid];
    __syncthreads();

    float acc[2][4][4] = {};

    for (int k0 = 0; k0 < S_; k0 += 32) {
        // P tile 128x32: read e, normalize, write back final attn, split hi/lo
        #pragma unroll
        for (int i = 0; i < 4; i++) {
            int idx = tid + i * 256;
            int r = idx >> 3, c = (idx & 7) << 2;
            float4 e4 = *(float4*)&Ab[(size_t)r * S_ + k0 + c];
            float inv = inv_s[r];
            e4.x *= inv; e4.y *= inv; e4.z *= inv; e4.w *= inv;
            *(float4*)&Ab[(size_t)r * S_ + k0 + c] = e4;
            uint32_t h01, l01, h23, l23;
            cvt_hilo2(e4.x, e4.y, h01, l01);
            cvt_hilo2(e4.z, e4.w, h23, l23);
            *(uint2*)&Ph[r][c] = make_uint2(h01, h23);
            *(uint2*)&Pl[r][c] = make_uint2(l01, l23);
        }
        // V tile 32(k) x 64(d) -> smem transposed [d][k]
        #pragma unroll
        for (int i = 0; i < 4; i++) {
            int j = tid + i * 256;              // 0..1023 u32 loads
            int d2 = j & 31, k = j >> 5;        // d = 2*d2
            uint32_t vh = *(const uint32_t*)&Vhg[(size_t)(k0 + k) * D_ + 2 * d2];
            uint32_t vl = *(const uint32_t*)&Vlg[(size_t)(k0 + k) * D_ + 2 * d2];
            Vh[2 * d2][k]     = __ushort_as_bfloat16((unsigned short)(vh & 0xffff));
            Vh[2 * d2 + 1][k] = __ushort_as_bfloat16((unsigned short)(vh >> 16));
            Vl[2 * d2][k]     = __ushort_as_bfloat16((unsigned short)(vl & 0xffff));
            Vl[2 * d2 + 1][k] = __ushort_as_bfloat16((unsigned short)(vl >> 16));
        }
        __syncthreads();

        #pragma unroll
        for (int ks = 0; ks < 2; ks++) {
            const int kq = ks * 16 + q2;
            uint32_t ah[2][4], al[2][4];
            #pragma unroll
            for (int mt = 0; mt < 2; mt++) {
                int m = wm * 32 + mt * 16 + rr;
                ah[mt][0] = *(const uint32_t*)&Ph[m][kq];
                ah[mt][1] = *(const uint32_t*)&Ph[m + 8][kq];
                ah[mt][2] = *(const uint32_t*)&Ph[m][kq + 8];
                ah[mt][3] = *(const uint32_t*)&Ph[m + 8][kq + 8];
                al[mt][0] = *(const uint32_t*)&Pl[m][kq];
                al[mt][1] = *(const uint32_t*)&Pl[m + 8][kq];
                al[mt][2] = *(const uint32_t*)&Pl[m][kq + 8];
                al[mt][3] = *(const uint32_t*)&Pl[m + 8][kq + 8];
            }
            #pragma unroll
            for (int nt = 0; nt < 4; nt++) {
                int n = wn * 32 + nt * 8 + rr;
                uint32_t bh[2] = { *(const uint32_t*)&Vh[n][kq],
                                   *(const uint32_t*)&Vh[n][kq + 8] };
                uint32_t bl[2] = { *(const uint32_t*)&Vl[n][kq],
                                   *(const uint32_t*)&Vl[n][kq + 8] };
                #pragma unroll
                for (int mt = 0; mt < 2; mt++) {
                    mma16816(acc[mt][nt], ah[mt], bh);
                    mma16816(acc[mt][nt], al[mt], bh);
                    mma16816(acc[mt][nt], ah[mt], bl);
                }
            }
        }
        __syncthreads();
    }

    #pragma unroll
    for (int mt = 0; mt < 2; mt++) {
        #pragma unroll
        for (int nt = 0; nt < 4; nt++) {
            int d = wn * 32 + nt * 8 + q2;
            #pragma unroll
            for (int rh = 0; rh < 2; rh++) {
                int m = t0 + wm * 32 + mt * 16 + rr + rh * 8;
                float* p = g_C + ((size_t)(b * T_ + m)) * E_ + h * D_ + d;
                *(float2*)p = make_float2(acc[mt][nt][rh * 2], acc[mt][nt][rh * 2 + 1]);
            }
        }
    }
}

// ---------------------------------------------------------------------------
extern "C" void kernel_launch(void* const* d_in, const int* in_sizes, int n_in,
                              void* d_out, int out_size)
{
    const float* src = (const float*)d_in[0];
    const float* tgt = (const float*)d_in[1];
    const float* Wq  = (const float*)d_in[2];
    const float* Wk  = (const float*)d_in[3];
    const float* Wv  = (const float*)d_in[4];
    const float* Wo  = (const float*)d_in[5];
    const float* bo  = (const float*)d_in[6];

    float* out  = (float*)d_out;
    float* attn = out + (size_t)BT * E_;

    __nv_bfloat16 *Qh, *Ql, *Kh, *Kl, *Vh, *Vl;
    float *Cp;
    cudaGetSymbolAddress((void**)&Qh, g_Qh);
    cudaGetSymbolAddress((void**)&Ql, g_Ql);
    cudaGetSymbolAddress((void**)&Kh, g_Kh);
    cudaGetSymbolAddress((void**)&Kl, g_Kl);
    cudaGetSymbolAddress((void**)&Vh, g_Vh);
    cudaGetSymbolAddress((void**)&Vl, g_Vl);
    cudaGetSymbolAddress((void**)&Cp, g_C);

    static bool attr_set = false;
    if (!attr_set) {
        cudaFuncSetAttribute(k_sco, cudaFuncAttributeMaxDynamicSharedMemorySize,
                             4 * 128 * LDQ * (int)sizeof(__nv_bfloat16));
        attr_set = true;
    }

    dim3 blk(256);
    dim3 gproj(E_ / 128, BT / 128);

    k_proj<true><<<gproj, blk>>>(tgt, Wq, nullptr, nullptr, Qh, Ql);
    k_proj<true><<<gproj, blk>>>(src, Wk, nullptr, nullptr, Kh, Kl);
    k_proj<true><<<gproj, blk>>>(src, Wv, nullptr, nullptr, Vh, Vl);

    k_sco<<<dim3(T_ / 128, Z_), blk, 4 * 128 * LDQ * sizeof(__nv_bfloat16)>>>(attn);

    k_ctx<<<dim3(T_ / 128, Z_), blk>>>(attn);

    k_proj<false><<<gproj, blk>>>(Cp, Wo, out, bo, nullptr, nullptr);
}